// round 7
// baseline (speedup 1.0000x reference)
#include <cuda_runtime.h>
#include <mma.h>
#include <cfloat>
#include <cstdint>

using namespace nvcuda;

#define BB 8
#define CC 64
#define NN 2048
#define MM 2048
#define KSEL 614

__device__ float g_pd[(size_t)BB * NN * MM];
__device__ float g_xx[BB * NN];
__device__ float g_yy[BB * MM];
__device__ float g_rowp_m[16 * BB * NN];
__device__ float g_rowp_z[16 * BB * NN];
__device__ float g_colp_m[16 * BB * MM];
__device__ float g_colp_z[16 * BB * MM];
__device__ float g_rowmax[BB * NN];
__device__ float g_rowinvZ[BB * NN];
__device__ float g_colmax[BB * MM];
__device__ float g_colinvZ[BB * MM];
__device__ float g_csp[32 * BB * MM];
__device__ float g_rsp[2 * BB * NN];
__device__ unsigned char g_maskSrc[BB * NN];
__device__ unsigned char g_maskTgt[BB * MM];
__device__ float g_valInlier[BB * NN];

__device__ __forceinline__ float cvt_tf32f(float v) {
    uint32_t r; asm("cvt.rna.tf32.f32 %0, %1;" : "=r"(r) : "f"(v));
    return __uint_as_float(r);
}

// ---------------- squared norms ----------------
__global__ void sqnorm_kernel(const float* __restrict__ src_emb,
                              const float* __restrict__ tgt_emb) {
    int idx = blockIdx.x * blockDim.x + threadIdx.x;
    int which = blockIdx.y;
    if (idx >= BB * 2048) return;
    int b = idx >> 11, p = idx & 2047;
    const float* e = (which ? tgt_emb : src_emb) + (size_t)b * CC * 2048 + p;
    float s = 0.f;
#pragma unroll
    for (int c = 0; c < CC; c++) { float v = e[(size_t)c * 2048]; s += v * v; }
    if (which) g_yy[idx] = s; else g_xx[idx] = s;
}

// ---------------- wmma tf32 GEMM: 128(n) x 128(m) tile, K=64, 3-term split -------
// smem: A_hi/A_lo/B_hi/B_lo each [32][132] floats (16896 B); stage reuses all 4.
#define LDMP 132
#define CHUNK_F (32 * LDMP)
__global__ __launch_bounds__(256) void gemm_pd_tc(const float* __restrict__ src,
                                                  const float* __restrict__ tgt) {
    extern __shared__ __align__(16) float dsm[];
    float* A_hi = dsm;
    float* A_lo = dsm + CHUNK_F;
    float* B_hi = dsm + 2 * CHUNK_F;
    float* B_lo = dsm + 3 * CHUNK_F;
    float* stage = dsm;                      // [128][132] after MMA

    int b = blockIdx.z;
    int m0 = blockIdx.x * 128, n0 = blockIdx.y * 128;
    int tid = threadIdx.x, w = tid >> 5;
    int wr = w >> 1, wc = w & 1;             // warp 32 rows x 64 cols

    wmma::fragment<wmma::accumulator, 16, 16, 8, float> acc[2][4];
#pragma unroll
    for (int i = 0; i < 2; i++)
#pragma unroll
        for (int j = 0; j < 4; j++) wmma::fill_fragment(acc[i][j], 0.f);

    int lk = tid >> 3, loff = (tid & 7) * 16;   // thread: k-row lk, 16 cols at loff

    for (int ch = 0; ch < 2; ch++) {
        int kc = ch * 32;
        if (ch) __syncthreads();   // protect previous chunk's smem until consumed
        {
            const float* Sg = src + (size_t)b * CC * NN + (size_t)(kc + lk) * NN + n0 + loff;
            const float* Tg = tgt + (size_t)b * CC * MM + (size_t)(kc + lk) * MM + m0 + loff;
#pragma unroll
            for (int q = 0; q < 4; q++) {
                float4 va = *(const float4*)(Sg + 4 * q);
                float4 vb = *(const float4*)(Tg + 4 * q);
                float4 ha, la, hb, lb;
                ha.x = cvt_tf32f(va.x); la.x = cvt_tf32f(va.x - ha.x);
                ha.y = cvt_tf32f(va.y); la.y = cvt_tf32f(va.y - ha.y);
                ha.z = cvt_tf32f(va.z); la.z = cvt_tf32f(va.z - ha.z);
                ha.w = cvt_tf32f(va.w); la.w = cvt_tf32f(va.w - ha.w);
                hb.x = cvt_tf32f(vb.x); lb.x = cvt_tf32f(vb.x - hb.x);
                hb.y = cvt_tf32f(vb.y); lb.y = cvt_tf32f(vb.y - hb.y);
                hb.z = cvt_tf32f(vb.z); lb.z = cvt_tf32f(vb.z - hb.z);
                hb.w = cvt_tf32f(vb.w); lb.w = cvt_tf32f(vb.w - hb.w);
                int o = lk * LDMP + loff + 4 * q;
                *(float4*)(A_hi + o) = ha; *(float4*)(A_lo + o) = la;
                *(float4*)(B_hi + o) = hb; *(float4*)(B_lo + o) = lb;
            }
        }
        __syncthreads();
#pragma unroll
        for (int t = 0; t < 3; t++) {
            const float* Ap = (t == 2) ? A_lo : A_hi;
            const float* Bp = (t == 1) ? B_lo : B_hi;
#pragma unroll
            for (int k0 = 0; k0 < 32; k0 += 8) {
                wmma::fragment<wmma::matrix_a, 16, 16, 8, wmma::precision::tf32, wmma::col_major> af[2];
                wmma::fragment<wmma::matrix_b, 16, 16, 8, wmma::precision::tf32, wmma::row_major> bf[4];
#pragma unroll
                for (int i = 0; i < 2; i++)
                    wmma::load_matrix_sync(af[i], Ap + k0 * LDMP + wr * 32 + i * 16, LDMP);
#pragma unroll
                for (int j = 0; j < 4; j++)
                    wmma::load_matrix_sync(bf[j], Bp + k0 * LDMP + wc * 64 + j * 16, LDMP);
#pragma unroll
                for (int i = 0; i < 2; i++)
#pragma unroll
                    for (int j = 0; j < 4; j++)
                        wmma::mma_sync(acc[i][j], af[i], bf[j], acc[i][j]);
            }
        }
    }
    __syncthreads();
#pragma unroll
    for (int i = 0; i < 2; i++)
#pragma unroll
        for (int j = 0; j < 4; j++)
            wmma::store_matrix_sync(stage + (wr * 32 + i * 16) * LDMP + wc * 64 + j * 16,
                                    acc[i][j], LDMP, wmma::mem_row_major);
    __syncthreads();

    // finalize pd, write global, write back to stage for stats
    {
        int r = tid >> 1, ch = (tid & 1) * 64;
        float xv = g_xx[b * NN + n0 + r];
        float* prow = g_pd + (size_t)(b * NN + n0 + r) * MM + m0;
        float* srow = stage + r * LDMP;
#pragma unroll
        for (int q = 0; q < 16; q++) {
            int c = ch + 4 * q;
            float4 v = *(float4*)(srow + c);
            float4 y4 = *(const float4*)&g_yy[b * MM + m0 + c];
            float4 f;
            f.x = 2.f * v.x - xv - y4.x;
            f.y = 2.f * v.y - xv - y4.y;
            f.z = 2.f * v.z - xv - y4.z;
            f.w = 2.f * v.w - xv - y4.w;
            *(float4*)(prow + c) = f;
            *(float4*)(srow + c) = f;
        }
    }
    __syncthreads();

    if (tid < 128) {          // row stats over 128 cols
        const float* sr = stage + tid * LDMP;
        float mx = -FLT_MAX;
#pragma unroll 8
        for (int i = 0; i < 128; i++) mx = fmaxf(mx, sr[i]);
        float z = 0.f;
#pragma unroll 8
        for (int i = 0; i < 128; i++) z += __expf(sr[i] - mx);
        g_rowp_m[blockIdx.x * (BB * NN) + b * NN + n0 + tid] = mx;
        g_rowp_z[blockIdx.x * (BB * NN) + b * NN + n0 + tid] = z;
    } else {                  // col stats over 128 rows
        int c = tid - 128;
        float mx = -FLT_MAX;
#pragma unroll 8
        for (int r = 0; r < 128; r++) mx = fmaxf(mx, stage[r * LDMP + c]);
        float z = 0.f;
#pragma unroll 8
        for (int r = 0; r < 128; r++) z += __expf(stage[r * LDMP + c] - mx);
        g_colp_m[blockIdx.y * (BB * MM) + b * MM + m0 + c] = mx;
        g_colp_z[blockIdx.y * (BB * MM) + b * MM + m0 + c] = z;
    }
}

// ---------------- merge stat partials ----------------
__global__ void merge_stats_kernel() {
    int idx = blockIdx.x * blockDim.x + threadIdx.x;
    if (idx >= BB * 2048) return;
    if (blockIdx.y == 0) {
        float M = -FLT_MAX, Z = 0.f;
#pragma unroll
        for (int t = 0; t < 16; t++) {
            float m2 = g_rowp_m[t * (BB * NN) + idx], z2 = g_rowp_z[t * (BB * NN) + idx];
            float nm = fmaxf(M, m2);
            Z = Z * __expf(M - nm) + z2 * __expf(m2 - nm);
            M = nm;
        }
        g_rowmax[idx] = M; g_rowinvZ[idx] = 1.f / Z;
    } else {
        float M = -FLT_MAX, Z = 0.f;
#pragma unroll
        for (int t = 0; t < 16; t++) {
            float m2 = g_colp_m[t * (BB * MM) + idx], z2 = g_colp_z[t * (BB * MM) + idx];
            float nm = fmaxf(M, m2);
            Z = Z * __expf(M - nm) + z2 * __expf(m2 - nm);
            M = nm;
        }
        g_colmax[idx] = M; g_colinvZ[idx] = 1.f / Z;
    }
}

// ---------------- fused colSum + rowSum pass: 1024 cols x 64 rows, 512 blocks ------
__global__ __launch_bounds__(256) void cs_rs_kernel() {
    __shared__ float s_rm[64], s_riz[64];
    __shared__ float rs_w[8][64];
    int b = blockIdx.z, rt = blockIdx.y, ct = blockIdx.x;
    int tid = threadIdx.x, lane = tid & 31, warp = tid >> 5;
    int m = ct * 1024 + tid * 4;
    int r0 = rt * 64;
    if (tid < 64) {
        s_rm[tid]  = g_rowmax[b * NN + r0 + tid];
        s_riz[tid] = g_rowinvZ[b * NN + r0 + tid];
    }
    float4 cmx = *(const float4*)&g_colmax[b * MM + m];
    float4 ciz = *(const float4*)&g_colinvZ[b * MM + m];
    __syncthreads();
    float cs0 = 0.f, cs1 = 0.f, cs2 = 0.f, cs3 = 0.f;
    const float* base = g_pd + ((size_t)(b * NN + r0)) * MM + m;
    for (int g = 0; g < 16; g++) {
        float rs[4];
#pragma unroll
        for (int u = 0; u < 4; u++) {
            int n = g * 4 + u;
            float4 v = *(const float4*)(base + (size_t)n * MM);
            float rm = s_rm[n], riz = s_riz[n];
            cs0 += __expf(v.x - rm) * riz; cs1 += __expf(v.y - rm) * riz;
            cs2 += __expf(v.z - rm) * riz; cs3 += __expf(v.w - rm) * riz;
            rs[u] = __expf(v.x - cmx.x) * ciz.x + __expf(v.y - cmx.y) * ciz.y
                  + __expf(v.z - cmx.z) * ciz.z + __expf(v.w - cmx.w) * ciz.w;
        }
#pragma unroll
        for (int o = 16; o > 0; o >>= 1) {
            rs[0] += __shfl_xor_sync(0xffffffffu, rs[0], o);
            rs[1] += __shfl_xor_sync(0xffffffffu, rs[1], o);
            rs[2] += __shfl_xor_sync(0xffffffffu, rs[2], o);
            rs[3] += __shfl_xor_sync(0xffffffffu, rs[3], o);
        }
        if (lane == 0) {
            rs_w[warp][g * 4]     = rs[0];
            rs_w[warp][g * 4 + 1] = rs[1];
            rs_w[warp][g * 4 + 2] = rs[2];
            rs_w[warp][g * 4 + 3] = rs[3];
        }
    }
    __syncthreads();
    *(float4*)&g_csp[rt * (BB * MM) + b * MM + m] = make_float4(cs0, cs1, cs2, cs3);
    if (tid < 64) {
        float s = 0.f;
#pragma unroll
        for (int q = 0; q < 8; q++) s += rs_w[q][tid];
        g_rsp[ct * (BB * NN) + b * NN + r0 + tid] = s;
    }
}

// ---------------- per-batch k-th smallest ----------------
__global__ __launch_bounds__(256) void thresh_kernel(float* __restrict__ outMaskTgt,
                                                     float* __restrict__ outMaskSrc) {
    __shared__ float s[2048];
    __shared__ float vals[2048];
    int b = blockIdx.x, which = blockIdx.y, tid = threadIdx.x;
    if (which == 0) {
        for (int i = tid; i < 2048; i += 256) {
            float v = 0.f;
#pragma unroll
            for (int t = 0; t < 32; t++) v += g_csp[t * (BB * MM) + b * MM + i];
            vals[i] = v; s[i] = v;
        }
    } else {
        for (int i = tid; i < 2048; i += 256) {
            float v = g_rsp[b * NN + i] + g_rsp[BB * NN + b * NN + i];
            vals[i] = v; s[i] = v;
        }
    }
    __syncthreads();
    for (int k = 2; k <= 2048; k <<= 1) {
        for (int j = k >> 1; j > 0; j >>= 1) {
            for (int t = tid; t < 2048; t += 256) {
                int ixj = t ^ j;
                if (ixj > t) {
                    float a = s[t], c = s[ixj];
                    bool up = ((t & k) == 0);
                    if (up ? (a > c) : (a < c)) { s[t] = c; s[ixj] = a; }
                }
            }
            __syncthreads();
        }
    }
    float thresh = s[KSEL - 1];
    unsigned char* mb = which ? (g_maskSrc + b * 2048) : (g_maskTgt + b * 2048);
    float* mf = (which ? outMaskSrc : outMaskTgt) + b * 2048;
    for (int i = tid; i < 2048; i += 256) {
        bool mk = vals[i] < thresh;
        mb[i] = (unsigned char)mk;
        mf[i] = mk ? 1.0f : 0.0f;
    }
}

// ---------------- final row pass ----------------
__global__ __launch_bounds__(256) void final_row_kernel(const float* __restrict__ tgt,
                                                        float* __restrict__ outCorr) {
    __shared__ float sm[8][4];
    int row = blockIdx.x;
    int b = row >> 11, n = row & 2047;
    int tid = threadIdx.x, lane = tid & 31, w = tid >> 5;
    const float* p = g_pd + (size_t)row * MM;
    float rm = g_rowmax[row], riz = g_rowinvZ[row];
    int msrc = g_maskSrc[row];
    const unsigned char* mtgt = g_maskTgt + b * MM;
    const float* t0 = tgt + (size_t)b * 3 * MM;
    float cs = 0.f, d0 = 0.f, d1 = 0.f, d2 = 0.f;
    int m0 = tid * 8;
#pragma unroll
    for (int h = 0; h < 2; h++) {
        int m = m0 + h * 4;
        float4 v  = *(const float4*)(p + m);
        float4 ta = *(const float4*)(t0 + m);
        float4 tb = *(const float4*)(t0 + MM + m);
        float4 tc = *(const float4*)(t0 + 2 * MM + m);
        unsigned mk4 = *(const unsigned*)(mtgt + m);
        float vv[4]  = {v.x, v.y, v.z, v.w};
        float taa[4] = {ta.x, ta.y, ta.z, ta.w};
        float tbb[4] = {tb.x, tb.y, tb.z, tb.w};
        float tcc[4] = {tc.x, tc.y, tc.z, tc.w};
#pragma unroll
        for (int i = 0; i < 4; i++) {
            float e = __expf(vv[i] - rm);
            float sc = e * riz;
            bool keep = msrc || ((mk4 >> (8 * i)) & 1) || (e >= 1.0f);
            if (keep) { cs += sc; d0 += sc * taa[i]; d1 += sc * tbb[i]; d2 += sc * tcc[i]; }
        }
    }
#pragma unroll
    for (int o = 16; o > 0; o >>= 1) {
        cs += __shfl_xor_sync(0xffffffffu, cs, o);
        d0 += __shfl_xor_sync(0xffffffffu, d0, o);
        d1 += __shfl_xor_sync(0xffffffffu, d1, o);
        d2 += __shfl_xor_sync(0xffffffffu, d2, o);
    }
    if (lane == 0) { sm[w][0] = cs; sm[w][1] = d0; sm[w][2] = d1; sm[w][3] = d2; }
    __syncthreads();
    if (tid == 0) {
        float C = 0.f, D0 = 0.f, D1 = 0.f, D2 = 0.f;
#pragma unroll
        for (int q = 0; q < 8; q++) { C += sm[q][0]; D0 += sm[q][1]; D1 += sm[q][2]; D2 += sm[q][3]; }
        float denom = C < 1e-5f ? 1e-5f : C;
        float inv = 1.f / denom;
        outCorr[(size_t)(b * 3 + 0) * NN + n] = D0 * inv;
        outCorr[(size_t)(b * 3 + 1) * NN + n] = D1 * inv;
        outCorr[(size_t)(b * 3 + 2) * NN + n] = D2 * inv;
        g_valInlier[row] = msrc ? 0.f : (C * inv);
    }
}

// ---------------- src_weight normalize ----------------
__global__ __launch_bounds__(256) void src_weight_kernel(float* __restrict__ outW) {
    __shared__ float sm[256];
    int b = blockIdx.x, tid = threadIdx.x;
    float s = 0.f;
    for (int i = tid; i < 2048; i += 256) s += g_valInlier[b * 2048 + i];
    sm[tid] = s; __syncthreads();
    for (int st = 128; st > 0; st >>= 1) { if (tid < st) sm[tid] += sm[tid + st]; __syncthreads(); }
    float inv = 1.f / sm[0];
    for (int i = tid; i < 2048; i += 256) outW[b * 2048 + i] = g_valInlier[b * 2048 + i] * inv;
}

// ---------------- launch ----------------
extern "C" void kernel_launch(void* const* d_in, const int* in_sizes, int n_in,
                              void* d_out, int out_size) {
    const float* src_emb = (const float*)d_in[0];
    const float* tgt_emb = (const float*)d_in[1];
    const float* tgt = (const float*)d_in[3];

    float* out = (float*)d_out;
    float* outCorr    = out;
    float* outW       = out + BB * 3 * NN;
    float* outMaskSrc = outW + BB * NN;
    float* outMaskTgt = outMaskSrc + BB * NN;

    const int DSM = 4 * CHUNK_F * (int)sizeof(float);   // 67584 B
    cudaFuncSetAttribute(gemm_pd_tc, cudaFuncAttributeMaxDynamicSharedMemorySize, DSM);

    sqnorm_kernel<<<dim3((BB * 2048 + 255) / 256, 2), 256>>>(src_emb, tgt_emb);

    gemm_pd_tc<<<dim3(MM / 128, NN / 128, BB), 256, DSM>>>(src_emb, tgt_emb);

    merge_stats_kernel<<<dim3((BB * 2048 + 255) / 256, 2), 256>>>();

    cs_rs_kernel<<<dim3(2, 32, BB), 256>>>();

    thresh_kernel<<<dim3(BB, 2), 256>>>(outMaskTgt, outMaskSrc);

    final_row_kernel<<<BB * NN, 256>>>(tgt, outCorr);

    src_weight_kernel<<<BB, 256>>>(outW);
}

// round 8
// speedup vs baseline: 1.3800x; 1.3800x over previous
#include <cuda_runtime.h>
#include <cfloat>

#define BB 8
#define CC 64
#define NN 2048
#define MM 2048
#define KSEL 614

typedef unsigned long long ull;

__device__ float g_pd[(size_t)BB * NN * MM];
__device__ float g_xx[BB * NN];
__device__ float g_yy[BB * MM];
__device__ float g_rowp_m[16 * BB * NN];
__device__ float g_rowp_z[16 * BB * NN];
__device__ float g_colp_m[16 * BB * MM];
__device__ float g_colp_z[16 * BB * MM];
__device__ float g_rowmax[BB * NN];
__device__ float g_rowinvZ[BB * NN];
__device__ float g_colmax[BB * MM];
__device__ float g_colinvZ[BB * MM];
__device__ float g_csp[32 * BB * MM];
__device__ float g_rsp[2 * BB * NN];
__device__ unsigned char g_maskSrc[BB * NN];
__device__ unsigned char g_maskTgt[BB * MM];
__device__ float g_valInlier[BB * NN];

// ---------------- f32x2 helpers ----------------
__device__ __forceinline__ ull pack2(float x, float y) {
    ull r; asm("mov.b64 %0, {%1, %2};" : "=l"(r) : "f"(x), "f"(y)); return r;
}
__device__ __forceinline__ float2 unpack2(ull v) {
    float2 r; asm("mov.b64 {%0, %1}, %2;" : "=f"(r.x), "=f"(r.y) : "l"(v)); return r;
}
#define FMA2(d, a, b) asm("fma.rn.f32x2 %0, %1, %2, %0;" : "+l"(d) : "l"(a), "l"(b))

// ---------------- squared norms ----------------
__global__ void sqnorm_kernel(const float* __restrict__ src_emb,
                              const float* __restrict__ tgt_emb) {
    int idx = blockIdx.x * blockDim.x + threadIdx.x;
    int which = blockIdx.y;
    if (idx >= BB * 2048) return;
    int b = idx >> 11, p = idx & 2047;
    const float* e = (which ? tgt_emb : src_emb) + (size_t)b * CC * 2048 + p;
    float s = 0.f;
#pragma unroll
    for (int c = 0; c < CC; c++) { float v = e[(size_t)c * 2048]; s += v * v; }
    if (which) g_yy[idx] = s; else g_xx[idx] = s;
}

// ---------------- GEMM (FFMA2): 128(n) x 128(m) tile, fused stat partials ----------
__global__ __launch_bounds__(256) void gemm_pd_kernel(const float* __restrict__ src,
                                                      const float* __restrict__ tgt) {
    __shared__ __align__(16) char sbuf[49152];
    ull   (*As2)[16][128] = (ull(*)[16][128])sbuf;              // 2 x 16 x 128 ull = 32KB
    float (*Bs)[16][128]  = (float(*)[16][128])(sbuf + 32768);  // 2 x 16 x 128 f   = 16KB

    int b = blockIdx.z;
    int m0 = blockIdx.x * 128, n0 = blockIdx.y * 128;
    int tid = threadIdx.x;
    int tx = tid & 15, ty = tid >> 4;
    const float* Sg = src + (size_t)b * CC * NN + n0;
    const float* Tg = tgt + (size_t)b * CC * MM + m0;

    int lk = tid >> 4, lo = (tid & 15) * 8;

    ull acc[8][4];
#pragma unroll
    for (int j = 0; j < 8; j++)
#pragma unroll
        for (int i = 0; i < 4; i++) acc[j][i] = 0ull;

    float4 ra0, ra1, rb0, rb1;
    ra0 = *(const float4*)&Sg[(size_t)lk * NN + lo];
    ra1 = *(const float4*)&Sg[(size_t)lk * NN + lo + 4];
    rb0 = *(const float4*)&Tg[(size_t)lk * MM + lo];
    rb1 = *(const float4*)&Tg[(size_t)lk * MM + lo + 4];
    {
        ull* ar = &As2[0][lk][lo];
        ar[0] = pack2(ra0.x, ra0.x); ar[1] = pack2(ra0.y, ra0.y);
        ar[2] = pack2(ra0.z, ra0.z); ar[3] = pack2(ra0.w, ra0.w);
        ar[4] = pack2(ra1.x, ra1.x); ar[5] = pack2(ra1.y, ra1.y);
        ar[6] = pack2(ra1.z, ra1.z); ar[7] = pack2(ra1.w, ra1.w);
        *(float4*)&Bs[0][lk][lo] = rb0;
        *(float4*)&Bs[0][lk][lo + 4] = rb1;
    }
    __syncthreads();

    for (int s = 0; s < 4; s++) {
        if (s < 3) {
            int kk = 16 * (s + 1);
            ra0 = *(const float4*)&Sg[(size_t)(kk + lk) * NN + lo];
            ra1 = *(const float4*)&Sg[(size_t)(kk + lk) * NN + lo + 4];
            rb0 = *(const float4*)&Tg[(size_t)(kk + lk) * MM + lo];
            rb1 = *(const float4*)&Tg[(size_t)(kk + lk) * MM + lo + 4];
        }
        int buf = s & 1;
#pragma unroll
        for (int k = 0; k < 16; k++) {
            ull a[8];
            *(ulonglong2*)&a[0] = *(const ulonglong2*)&As2[buf][k][ty * 8];
            *(ulonglong2*)&a[2] = *(const ulonglong2*)&As2[buf][k][ty * 8 + 2];
            *(ulonglong2*)&a[4] = *(const ulonglong2*)&As2[buf][k][ty * 8 + 4];
            *(ulonglong2*)&a[6] = *(const ulonglong2*)&As2[buf][k][ty * 8 + 6];
            ull bv[4];
            *(ulonglong2*)&bv[0] = *(const ulonglong2*)&Bs[buf][k][tx * 8];
            *(ulonglong2*)&bv[2] = *(const ulonglong2*)&Bs[buf][k][tx * 8 + 4];
#pragma unroll
            for (int j = 0; j < 8; j++) {
                FMA2(acc[j][0], a[j], bv[0]);
                FMA2(acc[j][1], a[j], bv[1]);
                FMA2(acc[j][2], a[j], bv[2]);
                FMA2(acc[j][3], a[j], bv[3]);
            }
        }
        if (s < 3) {
            int nb = (s + 1) & 1;
            ull* ar = &As2[nb][lk][lo];
            ar[0] = pack2(ra0.x, ra0.x); ar[1] = pack2(ra0.y, ra0.y);
            ar[2] = pack2(ra0.z, ra0.z); ar[3] = pack2(ra0.w, ra0.w);
            ar[4] = pack2(ra1.x, ra1.x); ar[5] = pack2(ra1.y, ra1.y);
            ar[6] = pack2(ra1.z, ra1.z); ar[7] = pack2(ra1.w, ra1.w);
            *(float4*)&Bs[nb][lk][lo] = rb0;
            *(float4*)&Bs[nb][lk][lo + 4] = rb1;
            __syncthreads();
        }
    }

    // ---- epilogue: finalize pd, write, fused row/col stat partials ----
    int cg = m0 + tx * 8;
    float yv[8], xr[8];
    *(float4*)&yv[0] = *(const float4*)&g_yy[b * MM + cg];
    *(float4*)&yv[4] = *(const float4*)&g_yy[b * MM + cg + 4];
#pragma unroll
    for (int j = 0; j < 8; j++) xr[j] = g_xx[b * NN + n0 + ty * 8 + j];

    float cm[8];
#pragma unroll
    for (int i = 0; i < 8; i++) cm[i] = -FLT_MAX;
#pragma unroll
    for (int j = 0; j < 8; j++) {
#pragma unroll
        for (int i = 0; i < 4; i++) {
            float2 p = unpack2(acc[j][i]);
            cm[2 * i]     = fmaxf(cm[2 * i],     2.f * p.x - xr[j] - yv[2 * i]);
            cm[2 * i + 1] = fmaxf(cm[2 * i + 1], 2.f * p.y - xr[j] - yv[2 * i + 1]);
        }
    }

    float colz[8];
#pragma unroll
    for (int i = 0; i < 8; i++) colz[i] = 0.f;
#pragma unroll
    for (int j = 0; j < 8; j++) {
        float fr[8];
#pragma unroll
        for (int i = 0; i < 4; i++) {
            float2 p = unpack2(acc[j][i]);
            fr[2 * i]     = 2.f * p.x - xr[j] - yv[2 * i];
            fr[2 * i + 1] = 2.f * p.y - xr[j] - yv[2 * i + 1];
        }
        int n = n0 + ty * 8 + j;
        float* prow = g_pd + (size_t)(b * NN + n) * MM;
        *(float4*)&prow[cg]     = make_float4(fr[0], fr[1], fr[2], fr[3]);
        *(float4*)&prow[cg + 4] = make_float4(fr[4], fr[5], fr[6], fr[7]);

        float rmx = fr[0];
#pragma unroll
        for (int i = 1; i < 8; i++) rmx = fmaxf(rmx, fr[i]);
#pragma unroll
        for (int o = 1; o < 16; o <<= 1) rmx = fmaxf(rmx, __shfl_xor_sync(0xffffffffu, rmx, o));
        float rz = 0.f;
#pragma unroll
        for (int i = 0; i < 8; i++) rz += __expf(fr[i] - rmx);
#pragma unroll
        for (int o = 1; o < 16; o <<= 1) rz += __shfl_xor_sync(0xffffffffu, rz, o);
        if (tx == 0) {
            g_rowp_m[blockIdx.x * (BB * NN) + b * NN + n] = rmx;
            g_rowp_z[blockIdx.x * (BB * NN) + b * NN + n] = rz;
        }
#pragma unroll
        for (int i = 0; i < 8; i++) colz[i] += __expf(fr[i] - cm[i]);
    }

    __syncthreads();
    float* sm_m = (float*)sbuf;            // [16][128]
    float* sm_z = (float*)(sbuf + 8192);
#pragma unroll
    for (int i = 0; i < 8; i++) {
        sm_m[ty * 128 + tx * 8 + i] = cm[i];
        sm_z[ty * 128 + tx * 8 + i] = colz[i];
    }
    __syncthreads();
    if (tid < 128) {
        int c = tid;
        float M = -FLT_MAX;
#pragma unroll
        for (int t = 0; t < 16; t++) M = fmaxf(M, sm_m[t * 128 + c]);
        float Z = 0.f;
#pragma unroll
        for (int t = 0; t < 16; t++) Z += sm_z[t * 128 + c] * __expf(sm_m[t * 128 + c] - M);
        g_colp_m[blockIdx.y * (BB * MM) + b * MM + m0 + c] = M;
        g_colp_z[blockIdx.y * (BB * MM) + b * MM + m0 + c] = Z;
    }
}

// ---------------- merge stat partials ----------------
__global__ void merge_stats_kernel() {
    int idx = blockIdx.x * blockDim.x + threadIdx.x;
    if (idx >= BB * 2048) return;
    if (blockIdx.y == 0) {
        float M = -FLT_MAX, Z = 0.f;
#pragma unroll
        for (int t = 0; t < 16; t++) {
            float m2 = g_rowp_m[t * (BB * NN) + idx], z2 = g_rowp_z[t * (BB * NN) + idx];
            float nm = fmaxf(M, m2);
            Z = Z * __expf(M - nm) + z2 * __expf(m2 - nm);
            M = nm;
        }
        g_rowmax[idx] = M; g_rowinvZ[idx] = 1.f / Z;
    } else {
        float M = -FLT_MAX, Z = 0.f;
#pragma unroll
        for (int t = 0; t < 16; t++) {
            float m2 = g_colp_m[t * (BB * MM) + idx], z2 = g_colp_z[t * (BB * MM) + idx];
            float nm = fmaxf(M, m2);
            Z = Z * __expf(M - nm) + z2 * __expf(m2 - nm);
            M = nm;
        }
        g_colmax[idx] = M; g_colinvZ[idx] = 1.f / Z;
    }
}

// ---------------- fused colSum + rowSum pass: 1024 cols x 64 rows, 512 blocks ------
__global__ __launch_bounds__(256) void cs_rs_kernel() {
    __shared__ float s_rm[64], s_riz[64];
    __shared__ float rs_w[8][64];
    int b = blockIdx.z, rt = blockIdx.y, ct = blockIdx.x;
    int tid = threadIdx.x, lane = tid & 31, warp = tid >> 5;
    int m = ct * 1024 + tid * 4;
    int r0 = rt * 64;
    if (tid < 64) {
        s_rm[tid]  = g_rowmax[b * NN + r0 + tid];
        s_riz[tid] = g_rowinvZ[b * NN + r0 + tid];
    }
    float4 cmx = *(const float4*)&g_colmax[b * MM + m];
    float4 ciz = *(const float4*)&g_colinvZ[b * MM + m];
    __syncthreads();
    float cs0 = 0.f, cs1 = 0.f, cs2 = 0.f, cs3 = 0.f;
    const float* base = g_pd + ((size_t)(b * NN + r0)) * MM + m;
    for (int g = 0; g < 16; g++) {
        float rs[4];
#pragma unroll
        for (int u = 0; u < 4; u++) {
            int n = g * 4 + u;
            float4 v = *(const float4*)(base + (size_t)n * MM);
            float rm = s_rm[n], riz = s_riz[n];
            cs0 += __expf(v.x - rm) * riz; cs1 += __expf(v.y - rm) * riz;
            cs2 += __expf(v.z - rm) * riz; cs3 += __expf(v.w - rm) * riz;
            rs[u] = __expf(v.x - cmx.x) * ciz.x + __expf(v.y - cmx.y) * ciz.y
                  + __expf(v.z - cmx.z) * ciz.z + __expf(v.w - cmx.w) * ciz.w;
        }
#pragma unroll
        for (int o = 16; o > 0; o >>= 1) {
            rs[0] += __shfl_xor_sync(0xffffffffu, rs[0], o);
            rs[1] += __shfl_xor_sync(0xffffffffu, rs[1], o);
            rs[2] += __shfl_xor_sync(0xffffffffu, rs[2], o);
            rs[3] += __shfl_xor_sync(0xffffffffu, rs[3], o);
        }
        if (lane == 0) {
            rs_w[warp][g * 4]     = rs[0];
            rs_w[warp][g * 4 + 1] = rs[1];
            rs_w[warp][g * 4 + 2] = rs[2];
            rs_w[warp][g * 4 + 3] = rs[3];
        }
    }
    __syncthreads();
    *(float4*)&g_csp[rt * (BB * MM) + b * MM + m] = make_float4(cs0, cs1, cs2, cs3);
    if (tid < 64) {
        float s = 0.f;
#pragma unroll
        for (int q = 0; q < 8; q++) s += rs_w[q][tid];
        g_rsp[ct * (BB * NN) + b * NN + r0 + tid] = s;
    }
}

// ---------------- per-batch k-th smallest ----------------
__global__ __launch_bounds__(256) void thresh_kernel(float* __restrict__ outMaskTgt,
                                                     float* __restrict__ outMaskSrc) {
    __shared__ float s[2048];
    __shared__ float vals[2048];
    int b = blockIdx.x, which = blockIdx.y, tid = threadIdx.x;
    if (which == 0) {
        for (int i = tid; i < 2048; i += 256) {
            float v = 0.f;
#pragma unroll
            for (int t = 0; t < 32; t++) v += g_csp[t * (BB * MM) + b * MM + i];
            vals[i] = v; s[i] = v;
        }
    } else {
        for (int i = tid; i < 2048; i += 256) {
            float v = g_rsp[b * NN + i] + g_rsp[BB * NN + b * NN + i];
            vals[i] = v; s[i] = v;
        }
    }
    __syncthreads();
    for (int k = 2; k <= 2048; k <<= 1) {
        for (int j = k >> 1; j > 0; j >>= 1) {
            for (int t = tid; t < 2048; t += 256) {
                int ixj = t ^ j;
                if (ixj > t) {
                    float a = s[t], c = s[ixj];
                    bool up = ((t & k) == 0);
                    if (up ? (a > c) : (a < c)) { s[t] = c; s[ixj] = a; }
                }
            }
            __syncthreads();
        }
    }
    float thresh = s[KSEL - 1];
    unsigned char* mb = which ? (g_maskSrc + b * 2048) : (g_maskTgt + b * 2048);
    float* mf = (which ? outMaskSrc : outMaskTgt) + b * 2048;
    for (int i = tid; i < 2048; i += 256) {
        bool mk = vals[i] < thresh;
        mb[i] = (unsigned char)mk;
        mf[i] = mk ? 1.0f : 0.0f;
    }
}

// ---------------- final row pass ----------------
__global__ __launch_bounds__(256) void final_row_kernel(const float* __restrict__ tgt,
                                                        float* __restrict__ outCorr) {
    __shared__ float sm[8][4];
    int row = blockIdx.x;
    int b = row >> 11, n = row & 2047;
    int tid = threadIdx.x, lane = tid & 31, w = tid >> 5;
    const float* p = g_pd + (size_t)row * MM;
    float rm = g_rowmax[row], riz = g_rowinvZ[row];
    int msrc = g_maskSrc[row];
    const unsigned char* mtgt = g_maskTgt + b * MM;
    const float* t0 = tgt + (size_t)b * 3 * MM;
    float cs = 0.f, d0 = 0.f, d1 = 0.f, d2 = 0.f;
    int m0 = tid * 8;
#pragma unroll
    for (int h = 0; h < 2; h++) {
        int m = m0 + h * 4;
        float4 v  = *(const float4*)(p + m);
        float4 ta = *(const float4*)(t0 + m);
        float4 tb = *(const float4*)(t0 + MM + m);
        float4 tc = *(const float4*)(t0 + 2 * MM + m);
        unsigned mk4 = *(const unsigned*)(mtgt + m);
        float vv[4]  = {v.x, v.y, v.z, v.w};
        float taa[4] = {ta.x, ta.y, ta.z, ta.w};
        float tbb[4] = {tb.x, tb.y, tb.z, tb.w};
        float tcc[4] = {tc.x, tc.y, tc.z, tc.w};
#pragma unroll
        for (int i = 0; i < 4; i++) {
            float e = __expf(vv[i] - rm);
            float sc = e * riz;
            bool keep = msrc || ((mk4 >> (8 * i)) & 1) || (e >= 1.0f);
            if (keep) { cs += sc; d0 += sc * taa[i]; d1 += sc * tbb[i]; d2 += sc * tcc[i]; }
        }
    }
#pragma unroll
    for (int o = 16; o > 0; o >>= 1) {
        cs += __shfl_xor_sync(0xffffffffu, cs, o);
        d0 += __shfl_xor_sync(0xffffffffu, d0, o);
        d1 += __shfl_xor_sync(0xffffffffu, d1, o);
        d2 += __shfl_xor_sync(0xffffffffu, d2, o);
    }
    if (lane == 0) { sm[w][0] = cs; sm[w][1] = d0; sm[w][2] = d1; sm[w][3] = d2; }
    __syncthreads();
    if (tid == 0) {
        float C = 0.f, D0 = 0.f, D1 = 0.f, D2 = 0.f;
#pragma unroll
        for (int q = 0; q < 8; q++) { C += sm[q][0]; D0 += sm[q][1]; D1 += sm[q][2]; D2 += sm[q][3]; }
        float denom = C < 1e-5f ? 1e-5f : C;
        float inv = 1.f / denom;
        outCorr[(size_t)(b * 3 + 0) * NN + n] = D0 * inv;
        outCorr[(size_t)(b * 3 + 1) * NN + n] = D1 * inv;
        outCorr[(size_t)(b * 3 + 2) * NN + n] = D2 * inv;
        g_valInlier[row] = msrc ? 0.f : (C * inv);
    }
}

// ---------------- src_weight normalize ----------------
__global__ __launch_bounds__(256) void src_weight_kernel(float* __restrict__ outW) {
    __shared__ float sm[256];
    int b = blockIdx.x, tid = threadIdx.x;
    float s = 0.f;
    for (int i = tid; i < 2048; i += 256) s += g_valInlier[b * 2048 + i];
    sm[tid] = s; __syncthreads();
    for (int st = 128; st > 0; st >>= 1) { if (tid < st) sm[tid] += sm[tid + st]; __syncthreads(); }
    float inv = 1.f / sm[0];
    for (int i = tid; i < 2048; i += 256) outW[b * 2048 + i] = g_valInlier[b * 2048 + i] * inv;
}

// ---------------- launch ----------------
extern "C" void kernel_launch(void* const* d_in, const int* in_sizes, int n_in,
                              void* d_out, int out_size) {
    const float* src_emb = (const float*)d_in[0];
    const float* tgt_emb = (const float*)d_in[1];
    const float* tgt = (const float*)d_in[3];

    float* out = (float*)d_out;
    float* outCorr    = out;
    float* outW       = out + BB * 3 * NN;
    float* outMaskSrc = outW + BB * NN;
    float* outMaskTgt = outMaskSrc + BB * NN;

    sqnorm_kernel<<<dim3((BB * 2048 + 255) / 256, 2), 256>>>(src_emb, tgt_emb);

    gemm_pd_kernel<<<dim3(MM / 128, NN / 128, BB), 256>>>(src_emb, tgt_emb);

    merge_stats_kernel<<<dim3((BB * 2048 + 255) / 256, 2), 256>>>();

    cs_rs_kernel<<<dim3(2, 32, BB), 256>>>();

    thresh_kernel<<<dim3(BB, 2), 256>>>(outMaskTgt, outMaskSrc);

    final_row_kernel<<<BB * NN, 256>>>(tgt, outCorr);

    src_weight_kernel<<<BB, 256>>>(outW);
}